// round 1
// baseline (speedup 1.0000x reference)
#include <cuda_runtime.h>
#include <cstdint>

#define BT 8
#define SEQ 4096
#define NST 256
#define DIN 256
#define DOUT 256
#define M_TOT (BT*SEQ)          // 32768
#define CHUNK 64
#define NCHUNK (SEQ/CHUNK)      // 64

typedef unsigned long long u64;

// ---------------- device scratch (no allocs allowed) ----------------
__device__ float g_Bbar_r[NST*DIN];
__device__ float g_Bbar_i[NST*DIN];
__device__ float g_Ar[NST], g_Ai[NST];        // A_bar
__device__ float g_ALr[NST], g_ALi[NST];      // A_bar^CHUNK
__device__ float g_ur[M_TOT*NST];             // u real  [B,S,N]
__device__ float g_ui[M_TOT*NST];             // u imag
__device__ float g_hr[M_TOT*NST];             // h real
__device__ float g_hi[M_TOT*NST];             // h imag
__device__ float g_cr[BT*NCHUNK*NST], g_ci[BT*NCHUNK*NST];  // chunk-local end states
__device__ float g_pr[BT*NCHUNK*NST], g_pi[BT*NCHUNK*NST];  // incoming state per chunk

// ---------------- packed f32x2 helpers ----------------
__device__ __forceinline__ u64 pack2(float lo, float hi) {
    u64 r; asm("mov.b64 %0, {%1, %2};" : "=l"(r) : "f"(lo), "f"(hi)); return r;
}
__device__ __forceinline__ void ffma2(u64 &d, u64 a, u64 b) {
    asm("fma.rn.f32x2 %0, %1, %2, %0;" : "+l"(d) : "l"(a), "l"(b));
}
__device__ __forceinline__ float2 unpack2(u64 v) {
    float2 f; asm("mov.b64 {%0, %1}, %2;" : "=f"(f.x), "=f"(f.y) : "l"(v)); return f;
}

// ---------------- setup: discretization ----------------
__global__ void k_setup(const float* __restrict__ llr, const float* __restrict__ lim,
                        const float* __restrict__ ldt, const float* __restrict__ Bm) {
    int n = threadIdx.x;
    float lr = -expf(llr[n]);
    float li = lim[n];
    float dt = expf(ldt[n]);
    dt = fminf(fmaxf(dt, 0.005f), 0.1f);
    float dr = 1.f - 0.5f * dt * lr;     // denom real
    float di = -0.5f * dt * li;          // denom imag
    float nr = 1.f + 0.5f * dt * lr;     // num real
    float ni = 0.5f * dt * li;           // num imag
    float inv = 1.f / (dr*dr + di*di);
    float Ar = (nr*dr + ni*di) * inv;
    float Ai = (ni*dr - nr*di) * inv;
    g_Ar[n] = Ar; g_Ai[n] = Ai;
    float wr = dt * dr * inv;            // dt/denom
    float wi = -dt * di * inv;
    for (int k = 0; k < DIN; k++) {
        float b = Bm[n*DIN + k];
        g_Bbar_r[n*DIN + k] = wr * b;
        g_Bbar_i[n*DIN + k] = wi * b;
    }
    // A^CHUNK
    float pr = 1.f, pi = 0.f;
    for (int j = 0; j < CHUNK; j++) {
        float t = pr*Ar - pi*Ai;
        pi = pr*Ai + pi*Ar;
        pr = t;
    }
    g_ALr[n] = pr; g_ALi[n] = pi;
}

// ---------------- GEMM 1: u = x @ Bbar^T (real & imag) ----------------
// 64x64 tile, BK=16, 256 threads, 4x4 microtile per output set, f32x2 packed.
__global__ __launch_bounds__(256) void k_gemm_u(const float* __restrict__ x) {
    __shared__ float As[16][64];
    __shared__ float Brs[16][64];
    __shared__ float Bis[16][64];
    const int m0 = blockIdx.y * 64, n0 = blockIdx.x * 64;
    const int tid = threadIdx.x;
    const int lrow = tid >> 2;            // 0..63
    const int lcol = (tid & 3) << 2;      // 0,4,8,12
    const int ty = tid >> 4, tx = tid & 15;

    u64 accr[4][2], acci[4][2];
    #pragma unroll
    for (int i = 0; i < 4; i++) { accr[i][0]=0ull; accr[i][1]=0ull; acci[i][0]=0ull; acci[i][1]=0ull; }

    for (int k0 = 0; k0 < DIN; k0 += 16) {
        float4 av  = *(const float4*)&x[(size_t)(m0 + lrow)*DIN + k0 + lcol];
        float4 brv = *(const float4*)&g_Bbar_r[(n0 + lrow)*DIN + k0 + lcol];
        float4 biv = *(const float4*)&g_Bbar_i[(n0 + lrow)*DIN + k0 + lcol];
        __syncthreads();
        As [lcol+0][lrow]=av.x;  As [lcol+1][lrow]=av.y;  As [lcol+2][lrow]=av.z;  As [lcol+3][lrow]=av.w;
        Brs[lcol+0][lrow]=brv.x; Brs[lcol+1][lrow]=brv.y; Brs[lcol+2][lrow]=brv.z; Brs[lcol+3][lrow]=brv.w;
        Bis[lcol+0][lrow]=biv.x; Bis[lcol+1][lrow]=biv.y; Bis[lcol+2][lrow]=biv.z; Bis[lcol+3][lrow]=biv.w;
        __syncthreads();
        #pragma unroll
        for (int k = 0; k < 16; k++) {
            float4 a4 = *(float4*)&As[k][ty*4];
            float4 b4 = *(float4*)&Brs[k][tx*4];
            float4 c4 = *(float4*)&Bis[k][tx*4];
            u64 br0 = pack2(b4.x, b4.y), br1 = pack2(b4.z, b4.w);
            u64 bi0 = pack2(c4.x, c4.y), bi1 = pack2(c4.z, c4.w);
            float am[4] = {a4.x, a4.y, a4.z, a4.w};
            #pragma unroll
            for (int im = 0; im < 4; im++) {
                u64 avp = pack2(am[im], am[im]);
                ffma2(accr[im][0], avp, br0);
                ffma2(accr[im][1], avp, br1);
                ffma2(acci[im][0], avp, bi0);
                ffma2(acci[im][1], avp, bi1);
            }
        }
    }
    #pragma unroll
    for (int im = 0; im < 4; im++) {
        size_t row = (size_t)(m0 + ty*4 + im)*NST + n0 + tx*4;
        float2 r0 = unpack2(accr[im][0]), r1 = unpack2(accr[im][1]);
        *(float4*)&g_ur[row] = make_float4(r0.x, r0.y, r1.x, r1.y);
        float2 i0 = unpack2(acci[im][0]), i1 = unpack2(acci[im][1]);
        *(float4*)&g_ui[row] = make_float4(i0.x, i0.y, i1.x, i1.y);
    }
}

// ---------------- scan pass 1: local chunk scan ----------------
__global__ __launch_bounds__(256) void k_scan1() {
    const int b = blockIdx.x / NCHUNK, c = blockIdx.x % NCHUNK;
    const int n = threadIdx.x;
    const float Ar = g_Ar[n], Ai = g_Ai[n];
    size_t base = ((size_t)b*SEQ + (size_t)c*CHUNK)*NST + n;
    float hr = 0.f, hi = 0.f;
    #pragma unroll 8
    for (int j = 0; j < CHUNK; j++) {
        float ur = g_ur[base], ui = g_ui[base];
        float nhr = fmaf(Ar, hr, fmaf(-Ai, hi, ur));
        float nhi = fmaf(Ar, hi, fmaf( Ai, hr, ui));
        hr = nhr; hi = nhi;
        g_hr[base] = hr; g_hi[base] = hi;
        base += NST;
    }
    g_cr[(b*NCHUNK + c)*NST + n] = hr;
    g_ci[(b*NCHUNK + c)*NST + n] = hi;
}

// ---------------- scan pass 2: cross-chunk prefix (tiny) ----------------
__global__ __launch_bounds__(256) void k_scan2() {
    const int b = blockIdx.x;
    const int n = threadIdx.x;
    const float Ar = g_ALr[n], Ai = g_ALi[n];
    float hr = 0.f, hi = 0.f;
    for (int c = 0; c < NCHUNK; c++) {
        int idx = (b*NCHUNK + c)*NST + n;
        g_pr[idx] = hr; g_pi[idx] = hi;           // state entering chunk c
        float cr = g_cr[idx], ci = g_ci[idx];
        float nhr = fmaf(Ar, hr, fmaf(-Ai, hi, cr));
        float nhi = fmaf(Ar, hi, fmaf( Ai, hr, ci));
        hr = nhr; hi = nhi;
    }
}

// ---------------- scan pass 3: inject carry into each chunk ----------------
__global__ __launch_bounds__(256) void k_scan3() {
    const int b = blockIdx.x / NCHUNK, c = blockIdx.x % NCHUNK;
    if (c == 0) return;                            // zero incoming state
    const int n = threadIdx.x;
    const float Ar = g_Ar[n], Ai = g_Ai[n];
    const float pr = g_pr[(b*NCHUNK + c)*NST + n];
    const float pi = g_pi[(b*NCHUNK + c)*NST + n];
    float powr = Ar, powi = Ai;                    // A^1
    size_t base = ((size_t)b*SEQ + (size_t)c*CHUNK)*NST + n;
    #pragma unroll 4
    for (int j = 0; j < CHUNK; j++) {
        float addr_ = powr*pr - powi*pi;
        float addi_ = powr*pi + powi*pr;
        g_hr[base] += addr_;
        g_hi[base] += addi_;
        float t = powr*Ar - powi*Ai;
        powi = powr*Ai + powi*Ar;
        powr = t;
        base += NST;
    }
}

// ---------------- GEMM 2: out = h_r @ C_r^T - h_i @ C_i^T ----------------
__global__ __launch_bounds__(256) void k_gemm_out(const float* __restrict__ Cr,
                                                  const float* __restrict__ Ci,
                                                  float* __restrict__ out) {
    __shared__ float Hr[16][64];
    __shared__ float Hi[16][64];
    __shared__ float Cs[16][64];
    __shared__ float Cn[16][64];   // -C_imag
    const int m0 = blockIdx.y * 64, d0 = blockIdx.x * 64;
    const int tid = threadIdx.x;
    const int lrow = tid >> 2;
    const int lcol = (tid & 3) << 2;
    const int ty = tid >> 4, tx = tid & 15;

    u64 acc[4][2];
    #pragma unroll
    for (int i = 0; i < 4; i++) { acc[i][0]=0ull; acc[i][1]=0ull; }

    for (int k0 = 0; k0 < NST; k0 += 16) {
        float4 hrv = *(const float4*)&g_hr[(size_t)(m0 + lrow)*NST + k0 + lcol];
        float4 hiv = *(const float4*)&g_hi[(size_t)(m0 + lrow)*NST + k0 + lcol];
        float4 crv = *(const float4*)&Cr[(d0 + lrow)*NST + k0 + lcol];
        float4 civ = *(const float4*)&Ci[(d0 + lrow)*NST + k0 + lcol];
        __syncthreads();
        Hr[lcol+0][lrow]=hrv.x; Hr[lcol+1][lrow]=hrv.y; Hr[lcol+2][lrow]=hrv.z; Hr[lcol+3][lrow]=hrv.w;
        Hi[lcol+0][lrow]=hiv.x; Hi[lcol+1][lrow]=hiv.y; Hi[lcol+2][lrow]=hiv.z; Hi[lcol+3][lrow]=hiv.w;
        Cs[lcol+0][lrow]=crv.x; Cs[lcol+1][lrow]=crv.y; Cs[lcol+2][lrow]=crv.z; Cs[lcol+3][lrow]=crv.w;
        Cn[lcol+0][lrow]=-civ.x; Cn[lcol+1][lrow]=-civ.y; Cn[lcol+2][lrow]=-civ.z; Cn[lcol+3][lrow]=-civ.w;
        __syncthreads();
        #pragma unroll
        for (int k = 0; k < 16; k++) {
            float4 a4 = *(float4*)&Hr[k][ty*4];
            float4 e4 = *(float4*)&Hi[k][ty*4];
            float4 c4 = *(float4*)&Cs[k][tx*4];
            float4 d4 = *(float4*)&Cn[k][tx*4];
            u64 c0 = pack2(c4.x, c4.y), c1 = pack2(c4.z, c4.w);
            u64 n0p = pack2(d4.x, d4.y), n1p = pack2(d4.z, d4.w);
            float am[4] = {a4.x, a4.y, a4.z, a4.w};
            float em[4] = {e4.x, e4.y, e4.z, e4.w};
            #pragma unroll
            for (int im = 0; im < 4; im++) {
                u64 avp = pack2(am[im], am[im]);
                u64 evp = pack2(em[im], em[im]);
                ffma2(acc[im][0], avp, c0);
                ffma2(acc[im][1], avp, c1);
                ffma2(acc[im][0], evp, n0p);
                ffma2(acc[im][1], evp, n1p);
            }
        }
    }
    #pragma unroll
    for (int im = 0; im < 4; im++) {
        size_t row = (size_t)(m0 + ty*4 + im)*DOUT + d0 + tx*4;
        float2 r0 = unpack2(acc[im][0]), r1 = unpack2(acc[im][1]);
        *(float4*)&out[row] = make_float4(r0.x, r0.y, r1.x, r1.y);
    }
}

// ---------------- launch ----------------
extern "C" void kernel_launch(void* const* d_in, const int* in_sizes, int n_in,
                              void* d_out, int out_size) {
    const float* x   = (const float*)d_in[0];
    const float* llr = (const float*)d_in[1];
    const float* lim = (const float*)d_in[2];
    const float* ldt = (const float*)d_in[3];
    const float* Bm  = (const float*)d_in[4];
    const float* Cr  = (const float*)d_in[5];
    const float* Ci  = (const float*)d_in[6];
    float* out = (float*)d_out;

    k_setup<<<1, 256>>>(llr, lim, ldt, Bm);
    k_gemm_u<<<dim3(NST/64, M_TOT/64), 256>>>(x);
    k_scan1<<<BT*NCHUNK, 256>>>();
    k_scan2<<<BT, 256>>>();
    k_scan3<<<BT*NCHUNK, 256>>>();
    k_gemm_out<<<dim3(DOUT/64, M_TOT/64), 256>>>(Cr, Ci, out);
}

// round 4
// speedup vs baseline: 1.3565x; 1.3565x over previous
#include <cuda_runtime.h>
#include <cuda_bf16.h>
#include <cstdint>

#define BT 8
#define SEQ 4096
#define NST 256
#define DIN 256
#define DOUT 256
#define M_TOT (BT*SEQ)          // 32768
#define CHUNK 64
#define NCHUNK (SEQ/CHUNK)      // 64

typedef unsigned long long u64;
typedef __nv_bfloat16 bf16;

// ---------------- device scratch ----------------
__device__ float g_Ar[NST], g_Ai[NST];
__device__ float g_ALr[NST], g_ALi[NST];
__device__ bf16  g_W1h[512*DIN], g_W1l[512*DIN];   // [Bbar_r; Bbar_i]
__device__ bf16  g_W2h[DOUT*512], g_W2l[DOUT*512]; // [Cr | -Ci]
__device__ float g_u[(size_t)M_TOT*512];      // u: [:,0:256]=real  [:,256:512]=imag
__device__ bf16  g_hh[(size_t)M_TOT*512];     // h hi: [hr | hi_part]
__device__ bf16  g_hl[(size_t)M_TOT*512];     // h lo
__device__ float g_cr[BT*NCHUNK*NST], g_ci[BT*NCHUNK*NST];
__device__ float g_pr[BT*NCHUNK*NST], g_pi[BT*NCHUNK*NST];

__device__ __forceinline__ void bsplit(float v, bf16& h, bf16& l) {
    h = __float2bfloat16(v);
    l = __float2bfloat16(v - __bfloat162float(h));
}

// mma.sync m16n8k16 row.col bf16 -> f32 accumulate
__device__ __forceinline__ void hmma(float* d, const uint32_t* a, const uint32_t* b) {
    asm volatile(
        "mma.sync.aligned.m16n8k16.row.col.f32.bf16.bf16.f32 "
        "{%0,%1,%2,%3}, {%4,%5,%6,%7}, {%8,%9}, {%0,%1,%2,%3};"
        : "+f"(d[0]), "+f"(d[1]), "+f"(d[2]), "+f"(d[3])
        : "r"(a[0]), "r"(a[1]), "r"(a[2]), "r"(a[3]), "r"(b[0]), "r"(b[1]));
}

// ---------------- setup ----------------
__global__ void k_setup(const float* __restrict__ llr, const float* __restrict__ lim,
                        const float* __restrict__ ldt, const float* __restrict__ Bm) {
    int n = threadIdx.x;
    float lr = -expf(llr[n]);
    float li = lim[n];
    float dt = expf(ldt[n]);
    dt = fminf(fmaxf(dt, 0.005f), 0.1f);
    float dr = 1.f - 0.5f * dt * lr;
    float di = -0.5f * dt * li;
    float nr = 1.f + 0.5f * dt * lr;
    float ni = 0.5f * dt * li;
    float inv = 1.f / (dr*dr + di*di);
    float Ar = (nr*dr + ni*di) * inv;
    float Ai = (ni*dr - nr*di) * inv;
    g_Ar[n] = Ar; g_Ai[n] = Ai;
    float wr = dt * dr * inv;
    float wi = -dt * di * inv;
    for (int k = 0; k < DIN; k++) {
        float b = Bm[n*DIN + k];
        bsplit(wr*b, g_W1h[n*DIN + k], g_W1l[n*DIN + k]);
        bsplit(wi*b, g_W1h[(256+n)*DIN + k], g_W1l[(256+n)*DIN + k]);
    }
    float pr = 1.f, pi = 0.f;
    for (int j = 0; j < CHUNK; j++) {
        float t = pr*Ar - pi*Ai;
        pi = pr*Ai + pi*Ar;
        pr = t;
    }
    g_ALr[n] = pr; g_ALi[n] = pi;
}

__global__ void k_w2(const float* __restrict__ Cr, const float* __restrict__ Ci) {
    int idx = blockIdx.x * blockDim.x + threadIdx.x;   // over 256*512
    int d = idx >> 9, k = idx & 511;
    float v = (k < 256) ? Cr[d*256 + k] : -Ci[d*256 + (k - 256)];
    bsplit(v, g_W2h[idx], g_W2l[idx]);
}

// ---------------- HMMA GEMM ----------------
// C[M, Ntot] = A @ W^T.
// CVT=true : A is fp32 [M, lda], converted to hi/lo in the smem stage.
// CVT=false: A given as bf16 hi/lo [M, lda].
// W[Ntot, Kdim] given as bf16 hi/lo. out fp32, leading dim ldc.
// Block tile 128(m) x 128(n), K chunk 64. 8 warps: warp_m = wid>>1 (32 rows),
// warp_n = wid&1 (64 cols). smem row stride 72 bf16.
#define SROW 72
#define TILE_BYTES (128*SROW*2)
#define SMEM_SZ (4*TILE_BYTES)

template<bool CVT>
__global__ __launch_bounds__(256, 2) void k_gemm(
    const void* __restrict__ Aptr, const bf16* __restrict__ Al_, int lda,
    const bf16* __restrict__ Wh, const bf16* __restrict__ Wl,
    float* __restrict__ out, int ldc, int Kdim)
{
    extern __shared__ bf16 smem[];
    bf16* Ah_s = smem;
    bf16* Al_s = smem + 128*SROW;
    bf16* Wh_s = smem + 2*128*SROW;
    bf16* Wl_s = smem + 3*128*SROW;

    const int tid = threadIdx.x;
    const int wid = tid >> 5, lane = tid & 31;
    const int m0 = blockIdx.y * 128;
    const int n0 = blockIdx.x * 128;
    const int wm = wid >> 1;            // 0..3 -> 32 rows each
    const int wn = wid & 1;             // 0..1 -> 64 cols each
    const int g  = lane >> 2;           // group row 0..7
    const int q4 = lane & 3;            // quad col

    float acc[2][8][4];
    #pragma unroll
    for (int i = 0; i < 2; i++)
        #pragma unroll
        for (int j = 0; j < 8; j++)
            #pragma unroll
            for (int r = 0; r < 4; r++) acc[i][j][r] = 0.f;

    const int nchunks = Kdim / 64;
    for (int ch = 0; ch < nchunks; ch++) {
        const int k0 = ch * 64;
        __syncthreads();
        // ---- stage A (128 rows x 64 cols = 8192 bf16 per tile) ----
        if (CVT) {
            const float* Af = (const float*)Aptr;
            #pragma unroll
            for (int i = 0; i < 8; i++) {
                int idx = tid + i * 256;            // 2048 quads of 4 floats
                int row = idx >> 4, q = idx & 15;
                float4 v = *(const float4*)&Af[(size_t)(m0 + row) * lda + k0 + q*4];
                bf16 h0,l0,h1,l1,h2,l2,h3,l3;
                bsplit(v.x,h0,l0); bsplit(v.y,h1,l1); bsplit(v.z,h2,l2); bsplit(v.w,h3,l3);
                __nv_bfloat162 hh0={h0,h1}, hh1={h2,h3}, ll0={l0,l1}, ll1={l2,l3};
                *(uint2*)&Ah_s[row*SROW + q*4] = make_uint2(*(uint32_t*)&hh0, *(uint32_t*)&hh1);
                *(uint2*)&Al_s[row*SROW + q*4] = make_uint2(*(uint32_t*)&ll0, *(uint32_t*)&ll1);
            }
        } else {
            const bf16* Ah = (const bf16*)Aptr;
            #pragma unroll
            for (int i = 0; i < 4; i++) {
                int idx = tid + i * 256;            // 1024 vecs of 8 bf16 = 8192
                int row = idx >> 3, q = idx & 7;
                *(uint4*)&Ah_s[row*SROW + q*8] = *(const uint4*)&Ah [(size_t)(m0 + row) * lda + k0 + q*8];
                *(uint4*)&Al_s[row*SROW + q*8] = *(const uint4*)&Al_[(size_t)(m0 + row) * lda + k0 + q*8];
            }
        }
        // ---- stage W (128 rows x 64 cols) ----
        #pragma unroll
        for (int i = 0; i < 4; i++) {
            int idx = tid + i * 256;
            int row = idx >> 3, q = idx & 7;
            *(uint4*)&Wh_s[row*SROW + q*8] = *(const uint4*)&Wh[(size_t)(n0 + row) * Kdim + k0 + q*8];
            *(uint4*)&Wl_s[row*SROW + q*8] = *(const uint4*)&Wl[(size_t)(n0 + row) * Kdim + k0 + q*8];
        }
        __syncthreads();

        // ---- compute: 4 k-steps of 16 ----
        #pragma unroll
        for (int ks = 0; ks < 4; ks++) {
            const int kk = ks * 16;
            uint32_t ah[2][4], al[2][4];
            #pragma unroll
            for (int mf = 0; mf < 2; mf++) {
                int row = wm*32 + mf*16 + g;
                int c = kk + q4*2;
                ah[mf][0] = *(uint32_t*)&Ah_s[ row     *SROW + c    ];
                ah[mf][1] = *(uint32_t*)&Ah_s[(row + 8)*SROW + c    ];
                ah[mf][2] = *(uint32_t*)&Ah_s[ row     *SROW + c + 8];
                ah[mf][3] = *(uint32_t*)&Ah_s[(row + 8)*SROW + c + 8];
                al[mf][0] = *(uint32_t*)&Al_s[ row     *SROW + c    ];
                al[mf][1] = *(uint32_t*)&Al_s[(row + 8)*SROW + c    ];
                al[mf][2] = *(uint32_t*)&Al_s[ row     *SROW + c + 8];
                al[mf][3] = *(uint32_t*)&Al_s[(row + 8)*SROW + c + 8];
            }
            #pragma unroll
            for (int nf = 0; nf < 8; nf++) {
                int nrow = wn*64 + nf*8 + g;
                int c = kk + q4*2;
                uint32_t bh[2], bl[2];
                bh[0] = *(uint32_t*)&Wh_s[nrow*SROW + c    ];
                bh[1] = *(uint32_t*)&Wh_s[nrow*SROW + c + 8];
                bl[0] = *(uint32_t*)&Wl_s[nrow*SROW + c    ];
                bl[1] = *(uint32_t*)&Wl_s[nrow*SROW + c + 8];
                #pragma unroll
                for (int mf = 0; mf < 2; mf++) {
                    hmma(acc[mf][nf], ah[mf], bh);
                    hmma(acc[mf][nf], ah[mf], bl);
                    hmma(acc[mf][nf], al[mf], bh);
                }
            }
        }
    }

    // ---- epilogue ----
    #pragma unroll
    for (int mf = 0; mf < 2; mf++) {
        int row = m0 + wm*32 + mf*16 + g;
        #pragma unroll
        for (int nf = 0; nf < 8; nf++) {
            int col = n0 + wn*64 + nf*8 + q4*2;
            *(float2*)&out[(size_t)row * ldc + col]       = make_float2(acc[mf][nf][0], acc[mf][nf][1]);
            *(float2*)&out[(size_t)(row + 8) * ldc + col] = make_float2(acc[mf][nf][2], acc[mf][nf][3]);
        }
    }
}

// ---------------- scan pass 1: chunk end states only ----------------
__global__ __launch_bounds__(256) void k_scan1() {
    const int b = blockIdx.x / NCHUNK, c = blockIdx.x % NCHUNK;
    const int n = threadIdx.x;
    const float Ar = g_Ar[n], Ai = g_Ai[n];
    size_t base = ((size_t)b*SEQ + (size_t)c*CHUNK) * 512 + n;
    float hr = 0.f, hi = 0.f;
    #pragma unroll 8
    for (int j = 0; j < CHUNK; j++) {
        float ur = g_u[base], ui = g_u[base + 256];
        float nhr = fmaf(Ar, hr, fmaf(-Ai, hi, ur));
        float nhi = fmaf(Ar, hi, fmaf( Ai, hr, ui));
        hr = nhr; hi = nhi;
        base += 512;
    }
    g_cr[(b*NCHUNK + c)*NST + n] = hr;
    g_ci[(b*NCHUNK + c)*NST + n] = hi;
}

// ---------------- scan pass 2: cross-chunk prefix, batched loads (MLP=16) ----------------
__global__ __launch_bounds__(256) void k_scan2() {
    const int b = blockIdx.x;
    const int n = threadIdx.x;
    const float Ar = g_ALr[n], Ai = g_ALi[n];
    float hr = 0.f, hi = 0.f;
    for (int cb = 0; cb < 4; cb++) {
        float cr[16], ci[16];
        #pragma unroll
        for (int i = 0; i < 16; i++) {
            int idx = (b*NCHUNK + cb*16 + i)*NST + n;
            cr[i] = g_cr[idx]; ci[i] = g_ci[idx];
        }
        #pragma unroll
        for (int i = 0; i < 16; i++) {
            int idx = (b*NCHUNK + cb*16 + i)*NST + n;
            g_pr[idx] = hr; g_pi[idx] = hi;
            float nhr = fmaf(Ar, hr, fmaf(-Ai, hi, cr[i]));
            float nhi = fmaf(Ar, hi, fmaf( Ai, hr, ci[i]));
            hr = nhr; hi = nhi;
        }
    }
}

// ---------------- scan pass 3: full scan with carry, emit h as bf16 hi/lo ----------------
__global__ __launch_bounds__(256) void k_scan3() {
    const int b = blockIdx.x / NCHUNK, c = blockIdx.x % NCHUNK;
    const int n = threadIdx.x;
    const float Ar = g_Ar[n], Ai = g_Ai[n];
    float hr = g_pr[(b*NCHUNK + c)*NST + n];
    float hi = g_pi[(b*NCHUNK + c)*NST + n];
    size_t base = ((size_t)b*SEQ + (size_t)c*CHUNK) * 512 + n;
    #pragma unroll 8
    for (int j = 0; j < CHUNK; j++) {
        float ur = g_u[base], ui = g_u[base + 256];
        float nhr = fmaf(Ar, hr, fmaf(-Ai, hi, ur));
        float nhi = fmaf(Ar, hi, fmaf( Ai, hr, ui));
        hr = nhr; hi = nhi;
        bsplit(hr, g_hh[base],       g_hl[base]);
        bsplit(hi, g_hh[base + 256], g_hl[base + 256]);
        base += 512;
    }
}

// ---------------- launch ----------------
extern "C" void kernel_launch(void* const* d_in, const int* in_sizes, int n_in,
                              void* d_out, int out_size) {
    const float* x   = (const float*)d_in[0];
    const float* llr = (const float*)d_in[1];
    const float* lim = (const float*)d_in[2];
    const float* ldt = (const float*)d_in[3];
    const float* Bm  = (const float*)d_in[4];
    const float* Cr  = (const float*)d_in[5];
    const float* Ci  = (const float*)d_in[6];
    float* out = (float*)d_out;

    cudaFuncSetAttribute(k_gemm<true>,  cudaFuncAttributeMaxDynamicSharedMemorySize, SMEM_SZ);
    cudaFuncSetAttribute(k_gemm<false>, cudaFuncAttributeMaxDynamicSharedMemorySize, SMEM_SZ);

    bf16 *w1h, *w1l, *w2h, *w2l, *hh, *hl;
    float *u;
    cudaGetSymbolAddress((void**)&w1h, g_W1h);
    cudaGetSymbolAddress((void**)&w1l, g_W1l);
    cudaGetSymbolAddress((void**)&w2h, g_W2h);
    cudaGetSymbolAddress((void**)&w2l, g_W2l);
    cudaGetSymbolAddress((void**)&hh, g_hh);
    cudaGetSymbolAddress((void**)&hl, g_hl);
    cudaGetSymbolAddress((void**)&u, g_u);

    k_setup<<<1, 256>>>(llr, lim, ldt, Bm);
    k_w2<<<(256*512)/256, 256>>>(Cr, Ci);
    // GEMM1: u[M,512] = x @ [Bbar_r;Bbar_i]^T   (x converted in-kernel)
    k_gemm<true><<<dim3(512/128, M_TOT/128), 256, SMEM_SZ>>>(x, nullptr, DIN, w1h, w1l, u, 512, DIN);
    k_scan1<<<BT*NCHUNK, 256>>>();
    k_scan2<<<BT, 256>>>();
    k_scan3<<<BT*NCHUNK, 256>>>();
    // GEMM2: out[M,256] = [hr|hi] @ [Cr|-Ci]^T
    k_gemm<false><<<dim3(DOUT/128, M_TOT/128), 256, SMEM_SZ>>>(hh, hl, 512, w2h, w2l, out, DOUT, 512);
}